// round 14
// baseline (speedup 1.0000x reference)
#include <cuda_runtime.h>
#include <cuda_fp16.h>
#include <math.h>
#include <stdint.h>

// Problem dims (fixed by the reference)
#define TT 4096   // tokens = B*S
#define DD 1024   // model dim
#define FF 4096   // ffn dim
#define EE 8      // experts
#define CC 512    // capacity

// ---------------- scratch (device globals; no runtime allocation) ----------------
__device__ float g_gate[TT];
__device__ int   g_expert[TT];
__device__ int   g_tok_of_slot[EE * CC];

// Plain fp16 operands everywhere (quant ~2.1e-4 RMS per tensor; 4 sources
// -> ~4.2e-4 total, 2.4x margin under the 1e-3 gate).
__device__ __align__(16) __half g_a[EE * CC * DD];
__device__ __align__(16) __half g_w1t[(size_t)EE * FF * DD];  // W1^T [E, F(N), D(K)]
__device__ __align__(16) __half g_w2t[(size_t)EE * DD * FF];  // W2^T [E, D(N), F(K)]
__device__ __align__(16) __half g_h[(size_t)EE * CC * FF];    // hidden

// ---------------- helpers (baseline sm_80+ features only) ----------------
__device__ __forceinline__ uint32_t smem_u32(const void* p) {
    uint32_t a;
    asm("{ .reg .u64 t; cvta.to.shared.u64 t, %1; cvt.u32.u64 %0, t; }" : "=r"(a) : "l"(p));
    return a;
}
__device__ __forceinline__ void cp_async16(uint32_t saddr, const void* gaddr) {
    asm volatile("cp.async.cg.shared.global [%0], [%1], 16;" :: "r"(saddr), "l"(gaddr) : "memory");
}
#define CP_COMMIT()  asm volatile("cp.async.commit_group;" ::: "memory")
#define CP_WAIT1()   asm volatile("cp.async.wait_group 1;" ::: "memory")

__device__ __forceinline__ void ldsm_x4(uint32_t* r, uint32_t addr) {
    asm volatile("ldmatrix.sync.aligned.m8n8.x4.shared.b16 {%0,%1,%2,%3}, [%4];"
                 : "=r"(r[0]), "=r"(r[1]), "=r"(r[2]), "=r"(r[3]) : "r"(addr));
}
__device__ __forceinline__ void mma16816(float* c, const uint32_t* a, const uint32_t* b) {
    asm volatile(
        "mma.sync.aligned.m16n8k16.row.col.f32.f16.f16.f32 "
        "{%0,%1,%2,%3}, {%4,%5,%6,%7}, {%8,%9}, {%0,%1,%2,%3};"
        : "+f"(c[0]), "+f"(c[1]), "+f"(c[2]), "+f"(c[3])
        : "r"(a[0]), "r"(a[1]), "r"(a[2]), "r"(a[3]), "r"(b[0]), "r"(b[1]));
}
#define SWZ128(o) ((o) ^ (((o) >> 3) & 0x70))

__device__ __forceinline__ float gelu_exact(float v) {
    return 0.5f * v * (1.0f + erff(v * 0.70710678118654752440f));
}
__device__ __forceinline__ uint32_t pack_h2(float a, float b) {
    __half2 h = __floats2half2_rn(a, b);
    return *reinterpret_cast<uint32_t*>(&h);
}

// ---------------- 1: fused init (zero out, slots=-1) + router ----------------
__global__ void init_router_kernel(float4* __restrict__ out4,
                                   const float* __restrict__ x,
                                   const float* __restrict__ wr,
                                   const float* __restrict__ br) {
    int i = blockIdx.x * 256 + threadIdx.x;
    out4[i] = make_float4(0.f, 0.f, 0.f, 0.f);
    if (i < EE * CC) g_tok_of_slot[i] = -1;

    int gw = (blockIdx.x * blockDim.x + threadIdx.x) >> 5;   // global warp = token
    int lane = threadIdx.x & 31;
    if (gw >= TT) return;
    const float* xt = x + (size_t)gw * DD;
    float acc[EE];
#pragma unroll
    for (int e = 0; e < EE; e++) acc[e] = 0.f;
    for (int d = lane; d < DD; d += 32) {
        float xv = xt[d];
        const float4* w4 = reinterpret_cast<const float4*>(wr + (size_t)d * EE);
        float4 wa = w4[0], wb = w4[1];
        acc[0] += xv * wa.x; acc[1] += xv * wa.y; acc[2] += xv * wa.z; acc[3] += xv * wa.w;
        acc[4] += xv * wb.x; acc[5] += xv * wb.y; acc[6] += xv * wb.z; acc[7] += xv * wb.w;
    }
#pragma unroll
    for (int e = 0; e < EE; e++)
#pragma unroll
        for (int o = 16; o > 0; o >>= 1) acc[e] += __shfl_xor_sync(0xffffffffu, acc[e], o);
    if (lane == 0) {
        float l[EE]; float best = -1e30f; int bi = 0;
#pragma unroll
        for (int e = 0; e < EE; e++) {
            l[e] = acc[e] + br[e];
            if (l[e] > best) { best = l[e]; bi = e; }
        }
        float s = 0.f;
#pragma unroll
        for (int e = 0; e < EE; e++) s += expf(l[e] - best);
        g_gate[gw] = 1.0f / s;
        g_expert[gw] = bi;
    }
}

// ---------------- 2: ordered capacity assignment (unchanged) ----------------
__global__ void assign_kernel() {
    __shared__ int s_warpcnt[EE][32], s_warpoff[EE][32], s_chunktot[EE], s_base[EE];
    int tid = threadIdx.x, lane = tid & 31, wid = tid >> 5;
    if (tid < EE) s_base[tid] = 0;
    for (int chunk = 0; chunk < TT; chunk += 1024) {
        __syncthreads();
        int t = chunk + tid;
        int e = g_expert[t];
        int inwarp = 0;
#pragma unroll
        for (int ee = 0; ee < EE; ee++) {
            unsigned m = __ballot_sync(0xffffffffu, e == ee);
            if (lane == 0) s_warpcnt[ee][wid] = __popc(m);
            if (e == ee) inwarp = __popc(m & ((1u << lane) - 1u));
        }
        __syncthreads();
        if (wid < EE) {
            int v = s_warpcnt[wid][lane], sc = v;
#pragma unroll
            for (int o = 1; o < 32; o <<= 1) {
                int n = __shfl_up_sync(0xffffffffu, sc, o);
                if (lane >= o) sc += n;
            }
            s_warpoff[wid][lane] = sc - v;
            if (lane == 31) s_chunktot[wid] = sc;
        }
        __syncthreads();
        int pos = s_base[e] + s_warpoff[e][wid] + inwarp + 1;  // 1-based (reference quirk)
        if (pos < CC) g_tok_of_slot[e * CC + pos] = t;
        else          g_gate[t] = 0.f;
        __syncthreads();
        if (tid < EE) s_base[tid] += s_chunktot[tid];
    }
}

// ---------------- 3: fused dispatch + wsplit(w1) + wsplit(w2) ----------------
#define DISP_BLKS (EE * CC)
#define W1_BLKS   ((FF / 32) * (DD / 32) * EE)
#define W2_BLKS   ((DD / 32) * (FF / 32) * EE)

__device__ __forceinline__ void wsplit_body(const float* __restrict__ Wp,
                                            __half* __restrict__ Wt,
                                            int R, int Cn, int bx, int by, size_t base) {
    __shared__ float t[32][33];
    int tx = threadIdx.x & 31, ty = threadIdx.x >> 5;   // 32 x 8
    int c  = bx * 32 + tx;
    int r0 = by * 32 + ty;
#pragma unroll
    for (int i = 0; i < 4; i++)
        t[ty + i * 8][tx] = Wp[(size_t)(r0 + i * 8) * Cn + c];
    __syncthreads();
    int oc = by * 32 + tx;                              // k index (orig row)
#pragma unroll
    for (int i = 0; i < 4; i++) {
        int orr = bx * 32 + ty + i * 8;                 // n index (orig col)
        Wt[base + (size_t)orr * R + oc] = __float2half_rn(t[tx][ty + i * 8]);
    }
}

__global__ void dispatch_wsplit_kernel(const float* __restrict__ x,
                                       const float* __restrict__ w1,
                                       const float* __restrict__ w2) {
    int b = blockIdx.x;
    if (b < DISP_BLKS) {
        int slot = b;
        int t = g_tok_of_slot[slot];
        int i = threadIdx.x;                             // 256 threads, 4 elems each
        uint2* da = reinterpret_cast<uint2*>(g_a + (size_t)slot * DD) + i;
        if (t < 0) { *da = make_uint2(0u, 0u); return; }
        float g = g_gate[t];
        float4 v = reinterpret_cast<const float4*>(x)[(size_t)t * (DD / 4) + i];
        *da = make_uint2(pack_h2(v.x * g, v.y * g), pack_h2(v.z * g, v.w * g));
    } else if (b < DISP_BLKS + W1_BLKS) {
        int idx = b - DISP_BLKS;
        int bx = idx % (FF / 32);
        int by = (idx / (FF / 32)) % (DD / 32);
        int e  = idx / ((FF / 32) * (DD / 32));
        wsplit_body(w1 + (size_t)e * DD * FF, g_w1t, DD, FF, bx, by, (size_t)e * DD * FF);
    } else {
        int idx = b - DISP_BLKS - W1_BLKS;
        int bx = idx % (DD / 32);
        int by = (idx / (DD / 32)) % (FF / 32);
        int e  = idx / ((DD / 32) * (FF / 32));
        wsplit_body(w2 + (size_t)e * FF * DD, g_w2t, FF, DD, bx, by, (size_t)e * FF * DD);
    }
}

// ---------------- 4/5: grouped GEMM, plain fp16, 1 MMA ----------------
// CTA tile 128(M)x128(N), K-chunk 64. 8 warps in 2(M)x4(N); warp tile 64x32.
// Stage = A(16KB) + B(16KB) = 32KB; NSTAGE=3 (96KB) -> 2 CTAs/SM.
// Round-9-proven schedule: wait(c) -> sync -> issue(c+2 into stage (c-1)%3) -> compute.
#define NSTAGE  3
#define STAGE_B 32768
#define TILE16K 16384
#define GEMM_SMEM (NSTAGE * STAGE_B)   // 98304 B

template <int KDIM, int NTOT, bool PHASE1>
__global__ void __launch_bounds__(256, 2)
moe_gemm_mma(const float* __restrict__ bias, float* __restrict__ outp) {
    extern __shared__ __align__(1024) char smem[];
    const uint32_t sbase = smem_u32(smem);
    const int tid = threadIdx.x;
    const int lane = tid & 31, warp = tid >> 5;
    const int wm = warp & 1, wn = warp >> 1;            // warp at (64*wm, 32*wn)
    const int e = blockIdx.z, bm = blockIdx.y, bn = blockIdx.x;

    const __half* A = (PHASE1 ? g_a : g_h) + ((size_t)e * CC + bm * 128) * KDIM;
    const __half* B = (PHASE1 ? g_w1t : g_w2t) + ((size_t)e * NTOT + bn * 128) * KDIM;

    // ldmatrix lane addressing (constant per thread)
    const uint32_t laneRowA = (lane & 7) + ((lane >> 3) & 1) * 8;   // + i*16 + wm*64
    const uint32_t laneKBA  = ((lane >> 4) & 1) * 16;               // k-byte block
    const uint32_t matB     = lane >> 3;
    const uint32_t laneRowB = (lane & 7) + (matB >> 1) * 8;         // + jp*16 + wn*32
    const uint32_t laneKBB  = (matB & 1) * 16;

    // Stage layout: [A 16KB | B 16KB], rows of 128B (64 fp16 k-values), SW128.
    auto issue_stage = [&](int c) {
        const uint32_t st = sbase + (c % NSTAGE) * STAGE_B;
        const int gk = c * 64;
#pragma unroll
        for (int q = 0; q < 4; q++) {
            int idx = tid + q * 256;                 // 0..1023
            int r = idx >> 3, j = idx & 7;
            size_t go = (size_t)r * KDIM + gk + j * 8;
            uint32_t so = SWZ128((uint32_t)(r * 128 + j * 16));
            cp_async16(st + 0 * TILE16K + so, A + go);
            cp_async16(st + 1 * TILE16K + so, B + go);
        }
        CP_COMMIT();
    };

    float acc[4][4][4];
#pragma unroll
    for (int i = 0; i < 4; i++)
#pragma unroll
        for (int j = 0; j < 4; j++)
#pragma unroll
            for (int q = 0; q < 4; q++) acc[i][j][q] = 0.f;

    issue_stage(0);
    issue_stage(1);

    constexpr int NCH = KDIM / 64;
    for (int c = 0; c < NCH; c++) {
        CP_WAIT1();                 // groups 0..c+1 issued; pending<=1 => group c done
        __syncthreads();            // visibility + proves stage (c-1)%3 fully consumed
        if (c + 2 < NCH) issue_stage(c + 2);   // into stage (c-1)%3: race-free
        else CP_COMMIT();                       // empty group keeps counts monotone
        const uint32_t ab = sbase + (c % NSTAGE) * STAGE_B;
        const uint32_t bb = ab + TILE16K;
#pragma unroll
        for (int s = 0; s < 4; s++) {               // 4 x k16 within the 64-k chunk
            uint32_t bf[4][2];
#pragma unroll
            for (int jp = 0; jp < 2; jp++) {
                uint32_t rB = wn * 32 + jp * 16 + laneRowB;
                uint32_t r4[4];
                ldsm_x4(r4, bb + SWZ128(rB * 128 + s * 32 + laneKBB));
                bf[jp * 2][0] = r4[0]; bf[jp * 2][1] = r4[1];
                bf[jp * 2 + 1][0] = r4[2]; bf[jp * 2 + 1][1] = r4[3];
            }
#pragma unroll
            for (int i = 0; i < 4; i++) {
                uint32_t ah[4];
                uint32_t rA = wm * 64 + i * 16 + laneRowA;
                ldsm_x4(ah, ab + SWZ128(rA * 128 + s * 32 + laneKBA));
#pragma unroll
                for (int j = 0; j < 4; j++)
                    mma16816(acc[i][j], ah, bf[j]);
            }
        }
        // no trailing barrier: next iteration's top barrier provides it
    }

    // ---------------- epilogue ----------------
    float2 bv[4];
#pragma unroll
    for (int j = 0; j < 4; j++) {
        int col = bn * 128 + wn * 32 + j * 8 + (lane & 3) * 2;
        bv[j] = *reinterpret_cast<const float2*>(bias + (size_t)e * NTOT + col);
    }

    if (PHASE1) {
#pragma unroll
        for (int i = 0; i < 4; i++) {
#pragma unroll
            for (int rr = 0; rr < 2; rr++) {
                int row = bm * 128 + wm * 64 + i * 16 + (lane >> 2) + rr * 8;
                size_t ro = ((size_t)e * CC + row) * NTOT;
#pragma unroll
                for (int j = 0; j < 4; j++) {
                    int col = bn * 128 + wn * 32 + j * 8 + (lane & 3) * 2;
                    float v0 = gelu_exact(acc[i][j][rr * 2 + 0] + bv[j].x);
                    float v1 = gelu_exact(acc[i][j][rr * 2 + 1] + bv[j].y);
                    *reinterpret_cast<uint32_t*>(g_h + ro + col) = pack_h2(v0, v1);
                }
            }
        }
    } else {
#pragma unroll
        for (int i = 0; i < 4; i++) {
#pragma unroll
            for (int rr = 0; rr < 2; rr++) {
                int row = bm * 128 + wm * 64 + i * 16 + (lane >> 2) + rr * 8;
                int t = g_tok_of_slot[e * CC + row];
                if (t < 0) continue;
                float g = g_gate[t];
#pragma unroll
                for (int j = 0; j < 4; j++) {
                    int col = bn * 128 + wn * 32 + j * 8 + (lane & 3) * 2;
                    float2 v;
                    v.x = g * (acc[i][j][rr * 2 + 0] + bv[j].x);
                    v.y = g * (acc[i][j][rr * 2 + 1] + bv[j].y);
                    *reinterpret_cast<float2*>(outp + (size_t)t * DD + col) = v;
                }
            }
        }
    }
}

// ---------------- launch (5 launches; GEMM1 is launch #4) ----------------
extern "C" void kernel_launch(void* const* d_in, const int* in_sizes, int n_in,
                              void* d_out, int out_size) {
    (void)in_sizes; (void)n_in; (void)out_size;
    const float* x  = (const float*)d_in[0];
    const float* wr = (const float*)d_in[1];
    const float* br = (const float*)d_in[2];
    const float* w1 = (const float*)d_in[3];
    const float* b1 = (const float*)d_in[4];
    const float* w2 = (const float*)d_in[5];
    const float* b2 = (const float*)d_in[6];
    float* out = (float*)d_out;

    cudaFuncSetAttribute(moe_gemm_mma<DD, FF, true>,
                         cudaFuncAttributeMaxDynamicSharedMemorySize, GEMM_SMEM);
    cudaFuncSetAttribute(moe_gemm_mma<FF, DD, false>,
                         cudaFuncAttributeMaxDynamicSharedMemorySize, GEMM_SMEM);

    init_router_kernel<<<(TT * DD / 4) / 256, 256>>>((float4*)out, x, wr, br);
    assign_kernel<<<1, 1024>>>();
    dispatch_wsplit_kernel<<<DISP_BLKS + W1_BLKS + W2_BLKS, 256>>>(x, w1, w2);
    moe_gemm_mma<DD, FF, true ><<<dim3(FF / 128, CC / 128, EE), 256, GEMM_SMEM>>>(b1, nullptr);
    moe_gemm_mma<FF, DD, false><<<dim3(DD / 128, CC / 128, EE), 256, GEMM_SMEM>>>(b2, out);
}

// round 15
// speedup vs baseline: 1.0063x; 1.0063x over previous
#include <cuda_runtime.h>
#include <cuda_fp16.h>
#include <math.h>
#include <stdint.h>

// Problem dims (fixed by the reference)
#define TT 4096   // tokens = B*S
#define DD 1024   // model dim
#define FF 4096   // ffn dim
#define EE 8      // experts
#define CC 512    // capacity

// ---------------- scratch (device globals; no runtime allocation) ----------------
__device__ float g_gate[TT];
__device__ int   g_expert[TT];
__device__ int   g_tok_of_slot[EE * CC];

// Plain fp16 operands everywhere (quant ~2.1e-4 RMS per tensor; 4 sources
// -> ~4.2e-4 total, 2.4x margin under the 1e-3 gate).
__device__ __align__(16) __half g_a[EE * CC * DD];
__device__ __align__(16) __half g_w1t[(size_t)EE * FF * DD];  // W1^T [E, F(N), D(K)]
__device__ __align__(16) __half g_w2t[(size_t)EE * DD * FF];  // W2^T [E, D(N), F(K)]
__device__ __align__(16) __half g_h[(size_t)EE * CC * FF];    // hidden

// ---------------- helpers (baseline sm_80+ features only) ----------------
__device__ __forceinline__ uint32_t smem_u32(const void* p) {
    uint32_t a;
    asm("{ .reg .u64 t; cvta.to.shared.u64 t, %1; cvt.u32.u64 %0, t; }" : "=r"(a) : "l"(p));
    return a;
}
__device__ __forceinline__ void cp_async16(uint32_t saddr, const void* gaddr) {
    asm volatile("cp.async.cg.shared.global [%0], [%1], 16;" :: "r"(saddr), "l"(gaddr) : "memory");
}
#define CP_COMMIT()  asm volatile("cp.async.commit_group;" ::: "memory")
#define CP_WAIT1()   asm volatile("cp.async.wait_group 1;" ::: "memory")

__device__ __forceinline__ void ldsm_x4(uint32_t* r, uint32_t addr) {
    asm volatile("ldmatrix.sync.aligned.m8n8.x4.shared.b16 {%0,%1,%2,%3}, [%4];"
                 : "=r"(r[0]), "=r"(r[1]), "=r"(r[2]), "=r"(r[3]) : "r"(addr));
}
__device__ __forceinline__ void mma16816(float* c, const uint32_t* a, const uint32_t* b) {
    asm volatile(
        "mma.sync.aligned.m16n8k16.row.col.f32.f16.f16.f32 "
        "{%0,%1,%2,%3}, {%4,%5,%6,%7}, {%8,%9}, {%0,%1,%2,%3};"
        : "+f"(c[0]), "+f"(c[1]), "+f"(c[2]), "+f"(c[3])
        : "r"(a[0]), "r"(a[1]), "r"(a[2]), "r"(a[3]), "r"(b[0]), "r"(b[1]));
}
#define SWZ128(o) ((o) ^ (((o) >> 3) & 0x70))

__device__ __forceinline__ float gelu_exact(float v) {
    return 0.5f * v * (1.0f + erff(v * 0.70710678118654752440f));
}
__device__ __forceinline__ uint32_t pack_h2(float a, float b) {
    __half2 h = __floats2half2_rn(a, b);
    return *reinterpret_cast<uint32_t*>(&h);
}

// ---------------- 1: fused init (zero out, slots=-1) + router ----------------
__global__ void init_router_kernel(float4* __restrict__ out4,
                                   const float* __restrict__ x,
                                   const float* __restrict__ wr,
                                   const float* __restrict__ br) {
    int i = blockIdx.x * 256 + threadIdx.x;
    out4[i] = make_float4(0.f, 0.f, 0.f, 0.f);
    if (i < EE * CC) g_tok_of_slot[i] = -1;

    int gw = (blockIdx.x * blockDim.x + threadIdx.x) >> 5;   // global warp = token
    int lane = threadIdx.x & 31;
    if (gw >= TT) return;
    const float* xt = x + (size_t)gw * DD;
    float acc[EE];
#pragma unroll
    for (int e = 0; e < EE; e++) acc[e] = 0.f;
    for (int d = lane; d < DD; d += 32) {
        float xv = xt[d];
        const float4* w4 = reinterpret_cast<const float4*>(wr + (size_t)d * EE);
        float4 wa = w4[0], wb = w4[1];
        acc[0] += xv * wa.x; acc[1] += xv * wa.y; acc[2] += xv * wa.z; acc[3] += xv * wa.w;
        acc[4] += xv * wb.x; acc[5] += xv * wb.y; acc[6] += xv * wb.z; acc[7] += xv * wb.w;
    }
#pragma unroll
    for (int e = 0; e < EE; e++)
#pragma unroll
        for (int o = 16; o > 0; o >>= 1) acc[e] += __shfl_xor_sync(0xffffffffu, acc[e], o);
    if (lane == 0) {
        float l[EE]; float best = -1e30f; int bi = 0;
#pragma unroll
        for (int e = 0; e < EE; e++) {
            l[e] = acc[e] + br[e];
            if (l[e] > best) { best = l[e]; bi = e; }
        }
        float s = 0.f;
#pragma unroll
        for (int e = 0; e < EE; e++) s += expf(l[e] - best);
        g_gate[gw] = 1.0f / s;
        g_expert[gw] = bi;
    }
}

// ---------------- 2: ordered capacity assignment (unchanged) ----------------
__global__ void assign_kernel() {
    __shared__ int s_warpcnt[EE][32], s_warpoff[EE][32], s_chunktot[EE], s_base[EE];
    int tid = threadIdx.x, lane = tid & 31, wid = tid >> 5;
    if (tid < EE) s_base[tid] = 0;
    for (int chunk = 0; chunk < TT; chunk += 1024) {
        __syncthreads();
        int t = chunk + tid;
        int e = g_expert[t];
        int inwarp = 0;
#pragma unroll
        for (int ee = 0; ee < EE; ee++) {
            unsigned m = __ballot_sync(0xffffffffu, e == ee);
            if (lane == 0) s_warpcnt[ee][wid] = __popc(m);
            if (e == ee) inwarp = __popc(m & ((1u << lane) - 1u));
        }
        __syncthreads();
        if (wid < EE) {
            int v = s_warpcnt[wid][lane], sc = v;
#pragma unroll
            for (int o = 1; o < 32; o <<= 1) {
                int n = __shfl_up_sync(0xffffffffu, sc, o);
                if (lane >= o) sc += n;
            }
            s_warpoff[wid][lane] = sc - v;
            if (lane == 31) s_chunktot[wid] = sc;
        }
        __syncthreads();
        int pos = s_base[e] + s_warpoff[e][wid] + inwarp + 1;  // 1-based (reference quirk)
        if (pos < CC) g_tok_of_slot[e * CC + pos] = t;
        else          g_gate[t] = 0.f;
        __syncthreads();
        if (tid < EE) s_base[tid] += s_chunktot[tid];
    }
}

// ---------------- 3: fused dispatch + wsplit(w1) + wsplit(w2) ----------------
#define DISP_BLKS (EE * CC)
#define W1_BLKS   ((FF / 32) * (DD / 32) * EE)
#define W2_BLKS   ((DD / 32) * (FF / 32) * EE)

__device__ __forceinline__ void wsplit_body(const float* __restrict__ Wp,
                                            __half* __restrict__ Wt,
                                            int R, int Cn, int bx, int by, size_t base) {
    __shared__ float t[32][33];
    int tx = threadIdx.x & 31, ty = threadIdx.x >> 5;   // 32 x 8
    int c  = bx * 32 + tx;
    int r0 = by * 32 + ty;
#pragma unroll
    for (int i = 0; i < 4; i++)
        t[ty + i * 8][tx] = Wp[(size_t)(r0 + i * 8) * Cn + c];
    __syncthreads();
    int oc = by * 32 + tx;                              // k index (orig row)
#pragma unroll
    for (int i = 0; i < 4; i++) {
        int orr = bx * 32 + ty + i * 8;                 // n index (orig col)
        Wt[base + (size_t)orr * R + oc] = __float2half_rn(t[tx][ty + i * 8]);
    }
}

__global__ void dispatch_wsplit_kernel(const float* __restrict__ x,
                                       const float* __restrict__ w1,
                                       const float* __restrict__ w2) {
    int b = blockIdx.x;
    if (b < DISP_BLKS) {
        int slot = b;
        int t = g_tok_of_slot[slot];
        int i = threadIdx.x;                             // 256 threads, 4 elems each
        uint2* da = reinterpret_cast<uint2*>(g_a + (size_t)slot * DD) + i;
        if (t < 0) { *da = make_uint2(0u, 0u); return; }
        float g = g_gate[t];
        float4 v = reinterpret_cast<const float4*>(x)[(size_t)t * (DD / 4) + i];
        *da = make_uint2(pack_h2(v.x * g, v.y * g), pack_h2(v.z * g, v.w * g));
    } else if (b < DISP_BLKS + W1_BLKS) {
        int idx = b - DISP_BLKS;
        int bx = idx % (FF / 32);
        int by = (idx / (FF / 32)) % (DD / 32);
        int e  = idx / ((FF / 32) * (DD / 32));
        wsplit_body(w1 + (size_t)e * DD * FF, g_w1t, DD, FF, bx, by, (size_t)e * DD * FF);
    } else {
        int idx = b - DISP_BLKS - W1_BLKS;
        int bx = idx % (DD / 32);
        int by = (idx / (DD / 32)) % (FF / 32);
        int e  = idx / ((DD / 32) * (FF / 32));
        wsplit_body(w2 + (size_t)e * FF * DD, g_w2t, FF, DD, bx, by, (size_t)e * FF * DD);
    }
}

// ---------------- 4/5: grouped GEMM, plain fp16, 1 MMA ----------------
// CTA tile 128(M)x128(N), K-chunk 64. 8 warps in 2(M)x4(N); warp tile 64x32.
// Stage = A(16KB) + B(16KB) = 32KB; NSTAGE=3 (96KB) -> 2 CTAs/SM.
// Round-9-proven schedule: wait(c) -> sync -> issue(c+2 into stage (c-1)%3) -> compute.
#define NSTAGE  3
#define STAGE_B 32768
#define TILE16K 16384
#define GEMM_SMEM (NSTAGE * STAGE_B)   // 98304 B

template <int KDIM, int NTOT, bool PHASE1>
__global__ void __launch_bounds__(256, 2)
moe_gemm_mma(const float* __restrict__ bias, float* __restrict__ outp) {
    extern __shared__ __align__(1024) char smem[];
    const uint32_t sbase = smem_u32(smem);
    const int tid = threadIdx.x;
    const int lane = tid & 31, warp = tid >> 5;
    const int wm = warp & 1, wn = warp >> 1;            // warp at (64*wm, 32*wn)
    const int e = blockIdx.z, bm = blockIdx.y, bn = blockIdx.x;

    const __half* A = (PHASE1 ? g_a : g_h) + ((size_t)e * CC + bm * 128) * KDIM;
    const __half* B = (PHASE1 ? g_w1t : g_w2t) + ((size_t)e * NTOT + bn * 128) * KDIM;

    // ldmatrix lane addressing (constant per thread)
    const uint32_t laneRowA = (lane & 7) + ((lane >> 3) & 1) * 8;   // + i*16 + wm*64
    const uint32_t laneKBA  = ((lane >> 4) & 1) * 16;               // k-byte block
    const uint32_t matB     = lane >> 3;
    const uint32_t laneRowB = (lane & 7) + (matB >> 1) * 8;         // + jp*16 + wn*32
    const uint32_t laneKBB  = (matB & 1) * 16;

    // Stage layout: [A 16KB | B 16KB], rows of 128B (64 fp16 k-values), SW128.
    auto issue_stage = [&](int c) {
        const uint32_t st = sbase + (c % NSTAGE) * STAGE_B;
        const int gk = c * 64;
#pragma unroll
        for (int q = 0; q < 4; q++) {
            int idx = tid + q * 256;                 // 0..1023
            int r = idx >> 3, j = idx & 7;
            size_t go = (size_t)r * KDIM + gk + j * 8;
            uint32_t so = SWZ128((uint32_t)(r * 128 + j * 16));
            cp_async16(st + 0 * TILE16K + so, A + go);
            cp_async16(st + 1 * TILE16K + so, B + go);
        }
        CP_COMMIT();
    };

    float acc[4][4][4];
#pragma unroll
    for (int i = 0; i < 4; i++)
#pragma unroll
        for (int j = 0; j < 4; j++)
#pragma unroll
            for (int q = 0; q < 4; q++) acc[i][j][q] = 0.f;

    issue_stage(0);
    issue_stage(1);

    constexpr int NCH = KDIM / 64;
    for (int c = 0; c < NCH; c++) {
        CP_WAIT1();                 // groups 0..c+1 issued; pending<=1 => group c done
        __syncthreads();            // visibility + proves stage (c-1)%3 fully consumed
        if (c + 2 < NCH) issue_stage(c + 2);   // into stage (c-1)%3: race-free
        else CP_COMMIT();                       // empty group keeps counts monotone
        const uint32_t ab = sbase + (c % NSTAGE) * STAGE_B;
        const uint32_t bb = ab + TILE16K;
#pragma unroll
        for (int s = 0; s < 4; s++) {               // 4 x k16 within the 64-k chunk
            uint32_t bf[4][2];
#pragma unroll
            for (int jp = 0; jp < 2; jp++) {
                uint32_t rB = wn * 32 + jp * 16 + laneRowB;
                uint32_t r4[4];
                ldsm_x4(r4, bb + SWZ128(rB * 128 + s * 32 + laneKBB));
                bf[jp * 2][0] = r4[0]; bf[jp * 2][1] = r4[1];
                bf[jp * 2 + 1][0] = r4[2]; bf[jp * 2 + 1][1] = r4[3];
            }
#pragma unroll
            for (int i = 0; i < 4; i++) {
                uint32_t ah[4];
                uint32_t rA = wm * 64 + i * 16 + laneRowA;
                ldsm_x4(ah, ab + SWZ128(rA * 128 + s * 32 + laneKBA));
#pragma unroll
                for (int j = 0; j < 4; j++)
                    mma16816(acc[i][j], ah, bf[j]);
            }
        }
        // no trailing barrier: next iteration's top barrier provides it
    }

    // ---------------- epilogue ----------------
    float2 bv[4];
#pragma unroll
    for (int j = 0; j < 4; j++) {
        int col = bn * 128 + wn * 32 + j * 8 + (lane & 3) * 2;
        bv[j] = *reinterpret_cast<const float2*>(bias + (size_t)e * NTOT + col);
    }

    if (PHASE1) {
#pragma unroll
        for (int i = 0; i < 4; i++) {
#pragma unroll
            for (int rr = 0; rr < 2; rr++) {
                int row = bm * 128 + wm * 64 + i * 16 + (lane >> 2) + rr * 8;
                size_t ro = ((size_t)e * CC + row) * NTOT;
#pragma unroll
                for (int j = 0; j < 4; j++) {
                    int col = bn * 128 + wn * 32 + j * 8 + (lane & 3) * 2;
                    float v0 = gelu_exact(acc[i][j][rr * 2 + 0] + bv[j].x);
                    float v1 = gelu_exact(acc[i][j][rr * 2 + 1] + bv[j].y);
                    *reinterpret_cast<uint32_t*>(g_h + ro + col) = pack_h2(v0, v1);
                }
            }
        }
    } else {
#pragma unroll
        for (int i = 0; i < 4; i++) {
#pragma unroll
            for (int rr = 0; rr < 2; rr++) {
                int row = bm * 128 + wm * 64 + i * 16 + (lane >> 2) + rr * 8;
                int t = g_tok_of_slot[e * CC + row];
                if (t < 0) continue;
                float g = g_gate[t];
#pragma unroll
                for (int j = 0; j < 4; j++) {
                    int col = bn * 128 + wn * 32 + j * 8 + (lane & 3) * 2;
                    float2 v;
                    v.x = g * (acc[i][j][rr * 2 + 0] + bv[j].x);
                    v.y = g * (acc[i][j][rr * 2 + 1] + bv[j].y);
                    *reinterpret_cast<float2*>(outp + (size_t)t * DD + col) = v;
                }
            }
        }
    }
}

// ---------------- launch (5 launches; GEMM1 is launch #4) ----------------
extern "C" void kernel_launch(void* const* d_in, const int* in_sizes, int n_in,
                              void* d_out, int out_size) {
    (void)in_sizes; (void)n_in; (void)out_size;
    const float* x  = (const float*)d_in[0];
    const float* wr = (const float*)d_in[1];
    const float* br = (const float*)d_in[2];
    const float* w1 = (const float*)d_in[3];
    const float* b1 = (const float*)d_in[4];
    const float* w2 = (const float*)d_in[5];
    const float* b2 = (const float*)d_in[6];
    float* out = (float*)d_out;

    cudaFuncSetAttribute(moe_gemm_mma<DD, FF, true>,
                         cudaFuncAttributeMaxDynamicSharedMemorySize, GEMM_SMEM);
    cudaFuncSetAttribute(moe_gemm_mma<FF, DD, false>,
                         cudaFuncAttributeMaxDynamicSharedMemorySize, GEMM_SMEM);

    init_router_kernel<<<(TT * DD / 4) / 256, 256>>>((float4*)out, x, wr, br);
    assign_kernel<<<1, 1024>>>();
    dispatch_wsplit_kernel<<<DISP_BLKS + W1_BLKS + W2_BLKS, 256>>>(x, w1, w2);
    moe_gemm_mma<DD, FF, true ><<<dim3(FF / 128, CC / 128, EE), 256, GEMM_SMEM>>>(b1, nullptr);
    moe_gemm_mma<FF, DD, false><<<dim3(DD / 128, CC / 128, EE), 256, GEMM_SMEM>>>(b2, out);
}